// round 6
// baseline (speedup 1.0000x reference)
#include <cuda_runtime.h>
#include <stdint.h>

// VTM downsampler — scalar fp32 FFMA, scale/bias folded into vertical coeffs.
// Exact: every vertical coefficient is int*2^-14 (or int*2^-7 for the phase-0
// column, absorbing the 128x horizontal delta); all partial sums are m*2^-14
// with |m| < 2^24, hence fp32-exact. floor(v) + clamp reproduces the int path.
//
// integer = i>>2, frac = 4*(i&3) -> FILTER rows {0,4,8,12}, taps k=3..8.
// Phase 0 = delta (128*center); phase 2 symmetric.

#define IH 1080
#define IW 1920
#define OH 540
#define OW 960
#define NIMG 24
#define XC 245           // staged cols: global -2..242 (local L = gcol+2)
#define XCP 248
#define NR 7             // staged rows 2B-2..2B+4 cover 8 output rows

// horizontal 6-tap (integer-valued results, exact in fp32)
#define HP1(a,b,c,d,e,f) fmaf(5.f,(a), fmaf(-18.f,(b), fmaf(114.f,(c), fmaf(36.f,(d), fmaf(-10.f,(e),(f))))))
#define HP2(a,b,c,d,e,f) fmaf(4.f,((a)+(f)), fmaf(-19.f,((b)+(e)), 79.f*((c)+(d))))
#define HP3(a,b,c,d,e,f) fmaf(5.f,(f), fmaf(-18.f,(e), fmaf(114.f,(d), fmaf(36.f,(c), fmaf(-10.f,(b),(a))))))

// vertical coefficients scaled by S (2^-14, or 2^-7 for the phase-0 column),
// rounding bias 0.5 seeded into the chain. All chains: 6 independent-phase FMAs.
#define V0(h,S)  fmaf(128.f*(S), h[bl+2], 0.5f)
#define V1(h,S)  fmaf(5.f*(S),h[bl+0], fmaf(-18.f*(S),h[bl+1], fmaf(114.f*(S),h[bl+2], \
                 fmaf(36.f*(S),h[bl+3], fmaf(-10.f*(S),h[bl+4], fmaf((S),h[bl+5], 0.5f))))))
#define V2(h,S)  fmaf(4.f*(S),(h[bl+0]+h[bl+5]), fmaf(-19.f*(S),(h[bl+1]+h[bl+4]), \
                 fmaf(79.f*(S),(h[bl+2]+h[bl+3]), 0.5f)))
#define V3(h,S)  fmaf(5.f*(S),h[bl+5], fmaf(-18.f*(S),h[bl+4], fmaf(114.f*(S),h[bl+3], \
                 fmaf(36.f*(S),h[bl+2], fmaf(-10.f*(S),h[bl+1], fmaf((S),h[bl+0], 0.5f))))))

#define S14 6.103515625e-5f   // 2^-14
#define S7  7.8125e-3f        // 2^-7  (phase-0 column: 128 folded in)

__device__ __forceinline__ float fin(float v) {
    return fminf(fmaxf(floorf(v), 0.f), 255.f);
}

__global__ __launch_bounds__(240, 6)
void vtm_down_kernel(const float* __restrict__ x, float* __restrict__ out) {
    const int bc = blockIdx.y;            // image 0..23
    const int B  = blockIdx.x;            // 8-output-row band, 0..67

    __shared__ float xt[NR][XCP];

    const int tid = threadIdx.x;          // 0..239 : output-col tile
    const float* xim = x + (size_t)bc * (IH * IW);
    const int r0 = 2 * B - 2;

    // ---- stage 7 x 245 clamped input window ----
    const int c0 = tid - 2 < 0 ? 0 : tid - 2;   // left clamp (tid<2 only)
    #pragma unroll
    for (int r = 0; r < NR; r++) {
        int gr = r0 + r; if (gr < 0) gr = 0;    // top clamp (B==0 only)
        const float* row = xim + (size_t)gr * IW;
        xt[r][tid] = __ldg(&row[c0]);
        if (tid < XC - 240) xt[r][240 + tid] = __ldg(&row[238 + tid]);
    }
    __syncthreads();

    // ---- horizontal: phase0 keeps raw center; phases 1..3 filtered ----
    float cv[NR], h1[NR], h2[NR], h3[NR];
    #pragma unroll
    for (int r = 0; r < NR; r++) {
        const float a = xt[r][tid];
        const float b = xt[r][tid + 1];
        const float c = xt[r][tid + 2];
        const float d = xt[r][tid + 3];
        const float e = xt[r][tid + 4];
        const float f = xt[r][tid + 5];
        cv[r] = c;                            // 128x folded into vertical coeffs
        h1[r] = HP1(a, b, c, d, e, f);
        h2[r] = HP2(a, b, c, d, e, f);
        h3[r] = HP3(a, b, c, d, e, f);
    }

    // ---- vertical: 2 bands x 4 phases, floor, clamp, float4 stores ----
    float* oim = out + (size_t)bc * (OH * OW) + (size_t)(8 * B) * OW + tid * 4;

    #pragma unroll
    for (int bl = 0; bl < 2; bl++) {
        if (8 * B + 4 * bl < OH) {
            float* op = oim + (size_t)(4 * bl) * OW;
            float4 o;
            // q = 0 (vertical delta): p0 output == input pixel, no epilogue needed
            o.x = cv[bl + 2];
            o.y = fin(V0(h1, S14)); o.z = fin(V0(h2, S14)); o.w = fin(V0(h3, S14));
            *(float4*)op = o;
            // q = 1
            o.x = fin(V1(cv, S7));  o.y = fin(V1(h1, S14));
            o.z = fin(V1(h2, S14)); o.w = fin(V1(h3, S14));
            *(float4*)(op + OW) = o;
            // q = 2 (symmetric)
            o.x = fin(V2(cv, S7));  o.y = fin(V2(h1, S14));
            o.z = fin(V2(h2, S14)); o.w = fin(V2(h3, S14));
            *(float4*)(op + 2 * OW) = o;
            // q = 3
            o.x = fin(V3(cv, S7));  o.y = fin(V3(h1, S14));
            o.z = fin(V3(h2, S14)); o.w = fin(V3(h3, S14));
            *(float4*)(op + 3 * OW) = o;
        }
    }
}

extern "C" void kernel_launch(void* const* d_in, const int* in_sizes, int n_in,
                              void* d_out, int out_size) {
    const float* x = (const float*)d_in[0];
    float* out = (float*)d_out;
    dim3 grid((OH + 7) / 8, NIMG);        // 68 x 24 = 1632 blocks
    vtm_down_kernel<<<grid, 240>>>(x, out);
}

// round 7
// speedup vs baseline: 1.0175x; 1.0175x over previous
#include <cuda_runtime.h>
#include <stdint.h>

// VTM downsampler — 16 output rows/block, float4 staging, scalar FFMA chains.
// Exact: all intermediates integer-valued * 2^-14 (or 2^-7), |units| < 2^24 ->
// fp32-exact; floor((acc+8192)/2^14) reproduced via folded coeffs + floorf.
//
// integer = i>>2, frac = 4*(i&3) -> FILTER rows {0,4,8,12}, taps k=3..8.

#define IH 1080
#define IW 1920
#define OH 540
#define OW 960
#define NIMG 24
#define XCP 248          // smem row: idx = gcol+4 (gcol -2..243 -> idx 2..247)
#define NR 9             // staged rows 4B-2 .. 4B+6 cover 16 output rows
#define NV4 61           // float4 staging items per row (gcol 0..243)

// horizontal 6-tap on window a..f = gcol u-2..u+3
#define HP1(a,b,c,d,e,f) fmaf(5.f,(a), fmaf(-18.f,(b), fmaf(114.f,(c), fmaf(36.f,(d), fmaf(-10.f,(e),(f))))))
#define HP2(a,b,c,d,e,f) fmaf(4.f,((a)+(f)), fmaf(-19.f,((b)+(e)), 79.f*((c)+(d))))
#define HP3(a,b,c,d,e,f) fmaf(5.f,(f), fmaf(-18.f,(e), fmaf(114.f,(d), fmaf(36.f,(c), fmaf(-10.f,(b),(a))))))

// vertical 6-tap on h[bl..bl+5], coeffs pre-scaled by S, rounding bias 0.5 seeded
#define V0(h,S)  fmaf(128.f*(S), h[(bl)+2], 0.5f)
#define V1(h,S)  fmaf(5.f*(S),h[(bl)+0], fmaf(-18.f*(S),h[(bl)+1], fmaf(114.f*(S),h[(bl)+2], \
                 fmaf(36.f*(S),h[(bl)+3], fmaf(-10.f*(S),h[(bl)+4], fmaf((S),h[(bl)+5], 0.5f))))))
#define V2(h,S)  fmaf(4.f*(S),(h[(bl)+0]+h[(bl)+5]), fmaf(-19.f*(S),(h[(bl)+1]+h[(bl)+4]), \
                 fmaf(79.f*(S),(h[(bl)+2]+h[(bl)+3]), 0.5f)))
#define V3(h,S)  fmaf(5.f*(S),h[(bl)+5], fmaf(-18.f*(S),h[(bl)+4], fmaf(114.f*(S),h[(bl)+3], \
                 fmaf(36.f*(S),h[(bl)+2], fmaf(-10.f*(S),h[(bl)+1], fmaf((S),h[(bl)+0], 0.5f))))))

#define S14 6.103515625e-5f   // 2^-14
#define S7  7.8125e-3f        // 2^-7  (phase-0 column: 128x folded in)

__device__ __forceinline__ float fin(float v) {
    return fminf(fmaxf(floorf(v), 0.f), 255.f);
}

// compute horizontal filters for staged row r into slot
#define HROW(r) do { \
    const float a = xt[r][tid + 2]; \
    const float b = xt[r][tid + 3]; \
    const float c = xt[r][tid + 4]; \
    const float d = xt[r][tid + 5]; \
    const float e = xt[r][tid + 6]; \
    const float f = xt[r][tid + 7]; \
    cv[r] = c; \
    h1[r] = HP1(a, b, c, d, e, f); \
    h2[r] = HP2(a, b, c, d, e, f); \
    h3[r] = HP3(a, b, c, d, e, f); \
} while (0)

// emit one 4-row output band using h[bl..bl+5]
#define BAND(bl) do { \
    float* op = oim + (size_t)(4 * (bl)) * OW; \
    float4 o; \
    o.x = cv[(bl) + 2]; \
    o.y = fin(V0(h1, S14)); o.z = fin(V0(h2, S14)); o.w = fin(V0(h3, S14)); \
    *(float4*)op = o; \
    o.x = fin(V1(cv, S7));  o.y = fin(V1(h1, S14)); \
    o.z = fin(V1(h2, S14)); o.w = fin(V1(h3, S14)); \
    *(float4*)(op + OW) = o; \
    o.x = fin(V2(cv, S7));  o.y = fin(V2(h1, S14)); \
    o.z = fin(V2(h2, S14)); o.w = fin(V2(h3, S14)); \
    *(float4*)(op + 2 * OW) = o; \
    o.x = fin(V3(cv, S7));  o.y = fin(V3(h1, S14)); \
    o.z = fin(V3(h2, S14)); o.w = fin(V3(h3, S14)); \
    *(float4*)(op + 3 * OW) = o; \
} while (0)

__global__ __launch_bounds__(240, 5)
void vtm_down_kernel(const float* __restrict__ x, float* __restrict__ out) {
    const int bc = blockIdx.y;            // image 0..23
    const int B  = blockIdx.x;            // 16-output-row band, 0..33

    __shared__ __align__(16) float xt[NR][XCP];

    const int tid = threadIdx.x;          // 0..239 : output-col tile
    const float* xim = x + (size_t)bc * (IH * IW);
    const int r0 = 4 * B - 2;             // global input row of local row 0

    // ---- stage NR x 244 via float4 (idx = gcol+4) ----
    for (int e = tid; e < NR * NV4; e += 240) {
        int r = e / NV4;
        int i = e - r * NV4;
        int gr = r0 + r; if (gr < 0) gr = 0;        // top clamp (B==0 only)
        const float4 v = *(const float4*)(xim + (size_t)gr * IW + 4 * i);
        *(float4*)&xt[r][4 * i + 4] = v;
    }
    if (tid < NR) {                                  // left-edge cols -2,-1 -> col 0
        int gr = r0 + tid; if (gr < 0) gr = 0;
        float v = __ldg(&xim[(size_t)gr * IW]);
        xt[tid][2] = v; xt[tid][3] = v;
    }
    __syncthreads();

    float cv[NR], h1[NR], h2[NR], h3[NR];
    float* oim = out + (size_t)bc * (OH * OW) + (size_t)(16 * B) * OW + tid * 4;
    const bool full = (16 * B + 16 <= OH);           // B < 33

    // rows 0..5 then band0; then one new row per band (keeps live regs low)
    HROW(0); HROW(1); HROW(2); HROW(3); HROW(4); HROW(5);
    { const int bl = 0; BAND(bl); }
    HROW(6);
    { const int bl = 1; BAND(bl); }
    HROW(7);
    { const int bl = 2; BAND(bl); }
    if (full) {                                      // last block: rows 540.. skipped
        HROW(8);
        const int bl = 3; BAND(bl);
    }
}

extern "C" void kernel_launch(void* const* d_in, const int* in_sizes, int n_in,
                              void* d_out, int out_size) {
    const float* x = (const float*)d_in[0];
    float* out = (float*)d_out;
    dim3 grid((OH + 15) / 16, NIMG);      // 34 x 24 = 816 blocks
    vtm_down_kernel<<<grid, 240>>>(x, out);
}